// round 6
// baseline (speedup 1.0000x reference)
#include <cuda_runtime.h>
#include <cuda_bf16.h>
#include <math.h>

// Problem constants
#define SEQ_LEN   512
#define PRED_LEN  96
#define PATCH_LEN 16
#define STRIDE    8
#define NQ        4
#define NLAYERS   3
#define NPATCH    63           // (512-16)/8+1
#define BATCH     32
#define CHANS     128
#define NCH       (BATCH*CHANS)        // 4096
#define FAN_IN    (NPATCH*NQ)          // 252
#define NPAIR     136                  // 16*17/2

typedef unsigned long long ull;

// ---- packed f32x2 helpers (sm_103a) ---------------------------------------
__device__ __forceinline__ ull fma2(ull a, ull b, ull c) {
    ull d; asm("fma.rn.f32x2 %0, %1, %2, %3;" : "=l"(d) : "l"(a), "l"(b), "l"(c)); return d;
}
__device__ __forceinline__ ull mul2(ull a, ull b) {
    ull d; asm("mul.rn.f32x2 %0, %1, %2;" : "=l"(d) : "l"(a), "l"(b)); return d;
}
__device__ __forceinline__ ull add2(ull a, ull b) {
    ull d; asm("add.rn.f32x2 %0, %1, %2;" : "=l"(d) : "l"(a), "l"(b)); return d;
}
__device__ __forceinline__ ull pack2(float lo, float hi) {
    ull d; asm("mov.b64 %0, {%1, %2};" : "=l"(d) : "f"(lo), "f"(hi)); return d;
}
__device__ __forceinline__ float lo2(ull a) { return __uint_as_float((unsigned)(a & 0xffffffffull)); }
__device__ __forceinline__ float hi2(ull a) { return __uint_as_float((unsigned)(a >> 32)); }

// Scratch (device globals; no allocation allowed)
__device__ float  d_encT[FAN_IN * NCH];         // enc transposed: [f][n]

// ---------------------------------------------------------------------------
// Kernel 1: encoder (UNCHANGED from round 4 -- known good).
// ---------------------------------------------------------------------------
__global__ __launch_bounds__(256) void enc_kernel(const float* __restrict__ x,
                                                  const float* __restrict__ weights) {
    __shared__ float2 sG[12][4];            // gate matrices m00,m01,m10,m11
    __shared__ float2 sU[16][16];           // sU[k][c]
    __shared__ ulonglong2 sM[NPAIR * 2];    // duplicated-packed quad forms

    int tid = threadIdx.x;

    if (tid < 12) {
        float phi   = weights[tid*3 + 0];
        float theta = weights[tid*3 + 1];
        float omega = weights[tid*3 + 2];
        float ct = cosf(0.5f*theta), st = sinf(0.5f*theta);
        float ap = 0.5f*(phi + omega);
        float am = 0.5f*(phi - omega);
        float cap = cosf(ap), sap = sinf(ap);
        float cam = cosf(am), sam = sinf(am);
        sG[tid][0] = make_float2( cap*ct, -sap*ct);   // m00
        sG[tid][1] = make_float2(-cam*st, -sam*st);   // m01
        sG[tid][2] = make_float2( cam*st, -sam*st);   // m10
        sG[tid][3] = make_float2( cap*ct,  sap*ct);   // m11
    }
    __syncthreads();

    if (tid < 16) {
        const int c = tid;
        float2 col[16];
        #pragma unroll
        for (int k = 0; k < 16; k++) col[k] = make_float2(k == c ? 1.f : 0.f, 0.f);

        #pragma unroll
        for (int l = 0; l < NLAYERS; l++) {
            #pragma unroll
            for (int w = 0; w < NQ; w++) {
                float2 m00 = sG[l*NQ + w][0], m01 = sG[l*NQ + w][1];
                float2 m10 = sG[l*NQ + w][2], m11 = sG[l*NQ + w][3];
                int bit = 1 << (3 - w);
                #pragma unroll
                for (int k0 = 0; k0 < 16; k0++) {
                    if (k0 & bit) continue;
                    int k1 = k0 | bit;
                    float2 a = col[k0], b = col[k1];
                    col[k0] = make_float2(m00.x*a.x - m00.y*a.y + m01.x*b.x - m01.y*b.y,
                                          m00.x*a.y + m00.y*a.x + m01.x*b.y + m01.y*b.x);
                    col[k1] = make_float2(m10.x*a.x - m10.y*a.y + m11.x*b.x - m11.y*b.y,
                                          m10.x*a.y + m10.y*a.x + m11.x*b.y + m11.y*b.x);
                }
            }
            int r = (l % (NQ - 1)) + 1;
            #pragma unroll
            for (int w = 0; w < NQ; w++) {
                int cb = 1 << (3 - w);
                int tb = 1 << (3 - ((w + r) & 3));
                #pragma unroll
                for (int k = 0; k < 16; k++) {
                    if ((k & cb) && !(k & tb)) {
                        float2 t = col[k]; col[k] = col[k | tb]; col[k | tb] = t;
                    }
                }
            }
        }
        #pragma unroll
        for (int k = 0; k < 16; k++) sU[k][c] = col[k];
    }
    __syncthreads();

    if (tid < NPAIR) {
        int a = 0, rem = tid;
        while (rem >= 16 - a) { rem -= 16 - a; a++; }
        int b = a + rem;

        float s[4] = {0.f, 0.f, 0.f, 0.f};
        #pragma unroll
        for (int k = 0; k < 16; k++) {
            float2 ua = sU[k][a], ub = sU[k][b];
            float re = ua.x*ub.x + ua.y*ub.y;
            #pragma unroll
            for (int i = 0; i < 4; i++)
                s[i] += ((k >> (3 - i)) & 1) ? -re : re;
        }
        float scale = (a == b) ? 1.f : 2.f;
        ulonglong2 q0, q1;
        q0.x = pack2(s[0]*scale, s[0]*scale); q0.y = pack2(s[1]*scale, s[1]*scale);
        q1.x = pack2(s[2]*scale, s[2]*scale); q1.y = pack2(s[3]*scale, s[3]*scale);
        sM[tid*2 + 0] = q0;
        sM[tid*2 + 1] = q1;
    }
    __syncthreads();

    int gtid = blockIdx.x * 256 + tid;      // grid = 63*2048 threads
    int h = gtid & 2047;
    int j = gtid >> 11;
    int n0 = h << 1;
    int b  = n0 >> 7;
    int m  = n0 & 127;

    const ull* xp = (const ull*)(x + (size_t)b * (SEQ_LEN*CHANS)
                                   + (size_t)(j*STRIDE) * CHANS + m);
    const ull EPS2 = 0x358637bd358637bdULL;   // (1e-6f, 1e-6f)

    ull v[16];
    #pragma unroll
    for (int k = 0; k < 16; k++)
        v[k] = add2(xp[k * (CHANS/2)], EPS2);

    ull z0 = 0ULL, z1 = 0ULL, z2 = 0ULL, z3 = 0ULL, nrm2 = 0ULL;
    int p = 0;
    #pragma unroll
    for (int a = 0; a < 16; a++) {
        #pragma unroll
        for (int bb = a; bb < 16; bb++) {
            ull u = mul2(v[a], v[bb]);
            if (bb == a) nrm2 = add2(nrm2, u);
            ulonglong2 q0 = sM[2*p + 0];
            ulonglong2 q1 = sM[2*p + 1];
            z0 = fma2(u, q0.x, z0);
            z1 = fma2(u, q0.y, z1);
            z2 = fma2(u, q1.x, z2);
            z3 = fma2(u, q1.y, z3);
            p++;
        }
    }
    float inv0 = 1.0f / lo2(nrm2);
    float inv1 = 1.0f / hi2(nrm2);
    ull inv2 = pack2(inv0, inv1);

    ull* e = (ull*)(d_encT + (size_t)(j*4) * NCH + n0);
    e[0*(NCH/2)] = mul2(z0, inv2);
    e[1*(NCH/2)] = mul2(z1, inv2);
    e[2*(NCH/2)] = mul2(z2, inv2);
    e[3*(NCH/2)] = mul2(z3, inv2);
}

// ---------------------------------------------------------------------------
// Kernel 2: fused head+skip GEMM, channel-packed f32x2 (corrected indexing).
// Block = 256 threads: cp = tid&63 -> channel pair (2cp, 2cp+1) [exact tile of
// 128 channels]; og = tid>>6 -> one of 4 output-pairs. Block covers 8 outputs
// x 1 batch. grid (12, 32) = 384 blocks / 3072 warps.
// Data loads: LDG.64 pre-packed (no movs); weights dup-packed in shared,
// broadcast LDS.128 gives both outputs of the pair. 4 instr / 8 MACs.
// One 32KB smem buffer reused head -> skip.
// ---------------------------------------------------------------------------
#define OPB 8   // outputs per block
__global__ __launch_bounds__(256) void out_kernel(
    const float* __restrict__ x,
    const float* __restrict__ head_w, const float* __restrict__ head_b,
    const float* __restrict__ skip_w, const float* __restrict__ skip_b,
    float* __restrict__ out)
{
    // sW[k][og] : ulonglong2 { dup w[o0+2og][k], dup w[o0+2og+1][k] }
    __shared__ ulonglong2 sW[SEQ_LEN * 4];   // 512*4*16B = 32KB, reused

    int tid = threadIdx.x;                   // 0..255
    int cp  = tid & 63;                      // channel pair
    int og  = tid >> 6;                      // output-pair group 0..3
    int b   = blockIdx.y;
    int o0  = blockIdx.x * OPB;

    // ---- stage head weights dup-packed: 252*8 floats ----
    {
        ull* sWu = (ull*)sW;
        for (int idx = tid; idx < FAN_IN * 8; idx += 256) {
            int f = idx % FAN_IN;            // consecutive tid -> consecutive f (coalesced)
            int r = idx / FAN_IN;            // 0..7 = output index within tile
            float w = head_w[(size_t)(o0 + r) * FAN_IN + f];
            // layout: sW[f*4 + (r>>1)] lanes: r even -> .x, r odd -> .y
            sWu[(f * 4 + (r >> 1)) * 2 + (r & 1)] = pack2(w, w);
        }
    }
    __syncthreads();

    int my_o = o0 + 2 * og;
    float bias0 = head_b[my_o]     + skip_b[my_o];
    float bias1 = head_b[my_o + 1] + skip_b[my_o + 1];
    ull acc0 = pack2(bias0, bias0);          // output my_o,   channels 2cp,2cp+1
    ull acc1 = pack2(bias1, bias1);          // output my_o+1, channels 2cp,2cp+1

    // ---- phase 1: head GEMM over encT ----
    const ull* ep = (const ull*)d_encT + (size_t)b * (CHANS/2) + cp;
    #pragma unroll 1
    for (int c = 0; c < FAN_IN / 12; c++) {          // 21 chunks of 12
        const int f0 = c * 12;
        ull ev[12];
        #pragma unroll
        for (int i = 0; i < 12; i++)
            ev[i] = __ldg(ep + (size_t)(f0 + i) * (NCH/2));
        #pragma unroll
        for (int i = 0; i < 12; i++) {
            ulonglong2 w = sW[(f0 + i) * 4 + og];
            acc0 = fma2(ev[i], w.x, acc0);
            acc1 = fma2(ev[i], w.y, acc1);
        }
    }
    __syncthreads();   // everyone done with head weights

    // ---- stage skip weights dup-packed: 512*8 floats ----
    {
        ull* sWu = (ull*)sW;
        for (int idx = tid; idx < SEQ_LEN * 8; idx += 256) {
            int l = idx & 511;               // consecutive tid -> consecutive l
            int r = idx >> 9;                // 0..7
            float w = skip_w[(size_t)(o0 + r) * SEQ_LEN + l];
            sWu[(l * 4 + (r >> 1)) * 2 + (r & 1)] = pack2(w, w);
        }
    }
    __syncthreads();

    // ---- phase 2: skip GEMM over x ----
    const ull* xp = (const ull*)x + (size_t)b * (SEQ_LEN * CHANS / 2) + cp;
    #pragma unroll 1
    for (int c = 0; c < SEQ_LEN / 16; c++) {         // 32 chunks of 16
        const int l0 = c * 16;
        ull xv[16];
        #pragma unroll
        for (int i = 0; i < 16; i++)
            xv[i] = __ldg(xp + (size_t)(l0 + i) * (CHANS/2));
        #pragma unroll
        for (int i = 0; i < 16; i++) {
            ulonglong2 w = sW[(l0 + i) * 4 + og];
            acc0 = fma2(xv[i], w.x, acc0);
            acc1 = fma2(xv[i], w.y, acc1);
        }
    }

    // ---- store: out[b][my_o..my_o+1][2cp..2cp+1] ----
    ull* op = (ull*)out + (size_t)b * (PRED_LEN * CHANS / 2) + (size_t)my_o * (CHANS/2) + cp;
    op[0]         = acc0;
    op[CHANS/2]   = acc1;
}

// ---------------------------------------------------------------------------
extern "C" void kernel_launch(void* const* d_in, const int* in_sizes, int n_in,
                              void* d_out, int out_size) {
    const float* x       = (const float*)d_in[0];
    const float* weights = (const float*)d_in[1];
    const float* head_w  = (const float*)d_in[2];
    const float* head_b  = (const float*)d_in[3];
    const float* skip_w  = (const float*)d_in[4];
    const float* skip_b  = (const float*)d_in[5];
    float* out = (float*)d_out;

    enc_kernel<<<(NPATCH * NCH / 2) / 256, 256>>>(x, weights);
    out_kernel<<<dim3(PRED_LEN / OPB, BATCH), 256>>>(x, head_w, head_b, skip_w, skip_b, out);
}

// round 7
// speedup vs baseline: 1.2662x; 1.2662x over previous
#include <cuda_runtime.h>
#include <cuda_bf16.h>
#include <math.h>

// Problem constants
#define SEQ_LEN   512
#define PRED_LEN  96
#define PATCH_LEN 16
#define STRIDE    8
#define NQ        4
#define NLAYERS   3
#define NPATCH    63           // (512-16)/8+1
#define BATCH     32
#define CHANS     128
#define NCH       (BATCH*CHANS)        // 4096
#define FAN_IN    (NPATCH*NQ)          // 252
#define NPAIR     136                  // 16*17/2

typedef unsigned long long ull;

// ---- packed f32x2 helpers (sm_103a) ---------------------------------------
__device__ __forceinline__ ull fma2(ull a, ull b, ull c) {
    ull d; asm("fma.rn.f32x2 %0, %1, %2, %3;" : "=l"(d) : "l"(a), "l"(b), "l"(c)); return d;
}
__device__ __forceinline__ ull mul2(ull a, ull b) {
    ull d; asm("mul.rn.f32x2 %0, %1, %2;" : "=l"(d) : "l"(a), "l"(b)); return d;
}
__device__ __forceinline__ ull add2(ull a, ull b) {
    ull d; asm("add.rn.f32x2 %0, %1, %2;" : "=l"(d) : "l"(a), "l"(b)); return d;
}
__device__ __forceinline__ ull pack2(float lo, float hi) {
    ull d; asm("mov.b64 %0, {%1, %2};" : "=l"(d) : "f"(lo), "f"(hi)); return d;
}
__device__ __forceinline__ float lo2(ull a) { return __uint_as_float((unsigned)(a & 0xffffffffull)); }
__device__ __forceinline__ float hi2(ull a) { return __uint_as_float((unsigned)(a >> 32)); }

// Scratch (device globals; no allocation allowed)
__device__ float  d_encT[FAN_IN * NCH];         // enc transposed: [f][n]

// ---------------------------------------------------------------------------
// Kernel 1: encoder (UNCHANGED -- known good).
// ---------------------------------------------------------------------------
__global__ __launch_bounds__(256) void enc_kernel(const float* __restrict__ x,
                                                  const float* __restrict__ weights) {
    __shared__ float2 sG[12][4];            // gate matrices m00,m01,m10,m11
    __shared__ float2 sU[16][16];           // sU[k][c]
    __shared__ ulonglong2 sM[NPAIR * 2];    // duplicated-packed quad forms

    int tid = threadIdx.x;

    if (tid < 12) {
        float phi   = weights[tid*3 + 0];
        float theta = weights[tid*3 + 1];
        float omega = weights[tid*3 + 2];
        float ct = cosf(0.5f*theta), st = sinf(0.5f*theta);
        float ap = 0.5f*(phi + omega);
        float am = 0.5f*(phi - omega);
        float cap = cosf(ap), sap = sinf(ap);
        float cam = cosf(am), sam = sinf(am);
        sG[tid][0] = make_float2( cap*ct, -sap*ct);   // m00
        sG[tid][1] = make_float2(-cam*st, -sam*st);   // m01
        sG[tid][2] = make_float2( cam*st, -sam*st);   // m10
        sG[tid][3] = make_float2( cap*ct,  sap*ct);   // m11
    }
    __syncthreads();

    if (tid < 16) {
        const int c = tid;
        float2 col[16];
        #pragma unroll
        for (int k = 0; k < 16; k++) col[k] = make_float2(k == c ? 1.f : 0.f, 0.f);

        #pragma unroll
        for (int l = 0; l < NLAYERS; l++) {
            #pragma unroll
            for (int w = 0; w < NQ; w++) {
                float2 m00 = sG[l*NQ + w][0], m01 = sG[l*NQ + w][1];
                float2 m10 = sG[l*NQ + w][2], m11 = sG[l*NQ + w][3];
                int bit = 1 << (3 - w);
                #pragma unroll
                for (int k0 = 0; k0 < 16; k0++) {
                    if (k0 & bit) continue;
                    int k1 = k0 | bit;
                    float2 a = col[k0], b = col[k1];
                    col[k0] = make_float2(m00.x*a.x - m00.y*a.y + m01.x*b.x - m01.y*b.y,
                                          m00.x*a.y + m00.y*a.x + m01.x*b.y + m01.y*b.x);
                    col[k1] = make_float2(m10.x*a.x - m10.y*a.y + m11.x*b.x - m11.y*b.y,
                                          m10.x*a.y + m10.y*a.x + m11.x*b.y + m11.y*b.x);
                }
            }
            int r = (l % (NQ - 1)) + 1;
            #pragma unroll
            for (int w = 0; w < NQ; w++) {
                int cb = 1 << (3 - w);
                int tb = 1 << (3 - ((w + r) & 3));
                #pragma unroll
                for (int k = 0; k < 16; k++) {
                    if ((k & cb) && !(k & tb)) {
                        float2 t = col[k]; col[k] = col[k | tb]; col[k | tb] = t;
                    }
                }
            }
        }
        #pragma unroll
        for (int k = 0; k < 16; k++) sU[k][c] = col[k];
    }
    __syncthreads();

    if (tid < NPAIR) {
        int a = 0, rem = tid;
        while (rem >= 16 - a) { rem -= 16 - a; a++; }
        int b = a + rem;

        float s[4] = {0.f, 0.f, 0.f, 0.f};
        #pragma unroll
        for (int k = 0; k < 16; k++) {
            float2 ua = sU[k][a], ub = sU[k][b];
            float re = ua.x*ub.x + ua.y*ub.y;
            #pragma unroll
            for (int i = 0; i < 4; i++)
                s[i] += ((k >> (3 - i)) & 1) ? -re : re;
        }
        float scale = (a == b) ? 1.f : 2.f;
        ulonglong2 q0, q1;
        q0.x = pack2(s[0]*scale, s[0]*scale); q0.y = pack2(s[1]*scale, s[1]*scale);
        q1.x = pack2(s[2]*scale, s[2]*scale); q1.y = pack2(s[3]*scale, s[3]*scale);
        sM[tid*2 + 0] = q0;
        sM[tid*2 + 1] = q1;
    }
    __syncthreads();

    int gtid = blockIdx.x * 256 + tid;      // grid = 63*2048 threads
    int h = gtid & 2047;
    int j = gtid >> 11;
    int n0 = h << 1;
    int b  = n0 >> 7;
    int m  = n0 & 127;

    const ull* xp = (const ull*)(x + (size_t)b * (SEQ_LEN*CHANS)
                                   + (size_t)(j*STRIDE) * CHANS + m);
    const ull EPS2 = 0x358637bd358637bdULL;   // (1e-6f, 1e-6f)

    ull v[16];
    #pragma unroll
    for (int k = 0; k < 16; k++)
        v[k] = add2(xp[k * (CHANS/2)], EPS2);

    ull z0 = 0ULL, z1 = 0ULL, z2 = 0ULL, z3 = 0ULL, nrm2 = 0ULL;
    int p = 0;
    #pragma unroll
    for (int a = 0; a < 16; a++) {
        #pragma unroll
        for (int bb = a; bb < 16; bb++) {
            ull u = mul2(v[a], v[bb]);
            if (bb == a) nrm2 = add2(nrm2, u);
            ulonglong2 q0 = sM[2*p + 0];
            ulonglong2 q1 = sM[2*p + 1];
            z0 = fma2(u, q0.x, z0);
            z1 = fma2(u, q0.y, z1);
            z2 = fma2(u, q1.x, z2);
            z3 = fma2(u, q1.y, z3);
            p++;
        }
    }
    float inv0 = 1.0f / lo2(nrm2);
    float inv1 = 1.0f / hi2(nrm2);
    ull inv2 = pack2(inv0, inv1);

    ull* e = (ull*)(d_encT + (size_t)(j*4) * NCH + n0);
    e[0*(NCH/2)] = mul2(z0, inv2);
    e[1*(NCH/2)] = mul2(z1, inv2);
    e[2*(NCH/2)] = mul2(z2, inv2);
    e[3*(NCH/2)] = mul2(z3, inv2);
}

// ---------------------------------------------------------------------------
// Kernel 2: fused head+skip GEMM, channel-packed f32x2, K-SPLIT across warp
// groups (no redundant global loads).
// Block = 256 threads: cp = tid&63 (channel pair, exact 128-channel tile),
// g = tid>>6 selects a k-quarter: head f in [g*63,(g+1)*63), skip l in
// [g*128,(g+1)*128). Each thread accumulates ALL 8 outputs of the tile for
// its k-quarter (8 f32x2 accs), then a shared-memory reduction sums the 4
// quarters. Every global word is loaded exactly once per block.
// grid (12, 32) = 384 blocks / 3072 warps.
// ---------------------------------------------------------------------------
#define OPB 8   // outputs per block
// sWbuf: dup-packed weights, k-major: [k=0..763][r=0..7] (head k<252, skip after)
// reused as reduction buffer (needs 16KB <= 47.8KB)
__global__ __launch_bounds__(256) void out_kernel(
    const float* __restrict__ x,
    const float* __restrict__ head_w, const float* __restrict__ head_b,
    const float* __restrict__ skip_w, const float* __restrict__ skip_b,
    float* __restrict__ out)
{
    __shared__ ull sW[(FAN_IN + SEQ_LEN) * OPB];   // 764*8*8B = 47.75KB

    int tid = threadIdx.x;                   // 0..255
    int cp  = tid & 63;                      // channel pair
    int g   = tid >> 6;                      // k-quarter 0..3
    int b   = blockIdx.y;
    int o0  = blockIdx.x * OPB;

    // ---- stage ALL weights dup-packed (once, no reuse sync) ----
    for (int idx = tid; idx < FAN_IN * OPB; idx += 256) {
        int r = idx / FAN_IN, f = idx - r * FAN_IN;
        float w = head_w[(size_t)(o0 + r) * FAN_IN + f];
        sW[f * OPB + r] = pack2(w, w);
    }
    for (int idx = tid; idx < SEQ_LEN * OPB; idx += 256) {
        int r = idx >> 9, l = idx & 511;
        float w = skip_w[(size_t)(o0 + r) * SEQ_LEN + l];
        sW[(FAN_IN + l) * OPB + r] = pack2(w, w);
    }
    __syncthreads();

    const ulonglong2* sW2 = (const ulonglong2*)sW;   // sW2[k*4 + j] = outputs 2j,2j+1

    ull acc[OPB];
    #pragma unroll
    for (int oo = 0; oo < OPB; oo++) acc[oo] = 0ULL;

    // ---- head quarter: f in [g*63, g*63+63), 7 chunks of 9 ----
    const ull* ep = (const ull*)d_encT + (size_t)b * (CHANS/2) + cp;
    {
        const int fbase = g * 63;
        #pragma unroll 1
        for (int c = 0; c < 7; c++) {
            const int f0 = fbase + c * 9;
            ull ev[9];
            #pragma unroll
            for (int i = 0; i < 9; i++)
                ev[i] = __ldg(ep + (size_t)(f0 + i) * (NCH/2));
            #pragma unroll
            for (int i = 0; i < 9; i++) {
                const int k = f0 + i;
                #pragma unroll
                for (int j = 0; j < 4; j++) {
                    ulonglong2 q = sW2[k*4 + j];
                    acc[2*j]   = fma2(ev[i], q.x, acc[2*j]);
                    acc[2*j+1] = fma2(ev[i], q.y, acc[2*j+1]);
                }
            }
        }
    }

    // ---- skip quarter: l in [g*128, g*128+128), 8 chunks of 16 ----
    const ull* xp = (const ull*)x + (size_t)b * (SEQ_LEN * CHANS / 2) + cp;
    {
        const int lbase = g * 128;
        #pragma unroll 1
        for (int c = 0; c < 8; c++) {
            const int l0 = lbase + c * 16;
            ull xv[16];
            #pragma unroll
            for (int i = 0; i < 16; i++)
                xv[i] = __ldg(xp + (size_t)(l0 + i) * (CHANS/2));
            #pragma unroll
            for (int i = 0; i < 16; i++) {
                const int k = FAN_IN + l0 + i;
                #pragma unroll
                for (int j = 0; j < 4; j++) {
                    ulonglong2 q = sW2[k*4 + j];
                    acc[2*j]   = fma2(xv[i], q.x, acc[2*j]);
                    acc[2*j+1] = fma2(xv[i], q.y, acc[2*j+1]);
                }
            }
        }
    }

    // ---- reduce 4 k-quarters via shared (reuse sW) ----
    __syncthreads();                         // all reads of sW done
    ull* sR = sW;                            // [g][cp][oo] : (g*64+cp)*8+oo, 16KB
    #pragma unroll
    for (int oo = 0; oo < OPB; oo++)
        sR[((size_t)g * 64 + cp) * OPB + oo] = acc[oo];
    __syncthreads();

    // thread (cp, g) finalizes outputs oo = 2g, 2g+1 for its channel pair
    #pragma unroll
    for (int t = 0; t < 2; t++) {
        int oo = 2 * g + t;
        ull s = add2(add2(sR[(0*64 + cp)*OPB + oo], sR[(1*64 + cp)*OPB + oo]),
                     add2(sR[(2*64 + cp)*OPB + oo], sR[(3*64 + cp)*OPB + oo]));
        float bias = head_b[o0 + oo] + skip_b[o0 + oo];
        s = add2(s, pack2(bias, bias));
        ull* op = (ull*)out + (size_t)b * (PRED_LEN * CHANS / 2)
                            + (size_t)(o0 + oo) * (CHANS/2) + cp;
        *op = s;
    }
}

// ---------------------------------------------------------------------------
extern "C" void kernel_launch(void* const* d_in, const int* in_sizes, int n_in,
                              void* d_out, int out_size) {
    const float* x       = (const float*)d_in[0];
    const float* weights = (const float*)d_in[1];
    const float* head_w  = (const float*)d_in[2];
    const float* head_b  = (const float*)d_in[3];
    const float* skip_w  = (const float*)d_in[4];
    const float* skip_b  = (const float*)d_in[5];
    float* out = (float*)d_out;

    enc_kernel<<<(NPATCH * NCH / 2) / 256, 256>>>(x, weights);
    out_kernel<<<dim3(PRED_LEN / OPB, BATCH), 256>>>(x, head_w, head_b, skip_w, skip_b, out);
}

// round 8
// speedup vs baseline: 1.3763x; 1.0870x over previous
#include <cuda_runtime.h>
#include <cuda_bf16.h>
#include <math.h>

// Problem constants
#define SEQ_LEN   512
#define PRED_LEN  96
#define PATCH_LEN 16
#define STRIDE    8
#define NQ        4
#define NLAYERS   3
#define NPATCH    63           // (512-16)/8+1
#define BATCH     32
#define CHANS     128
#define NCH       (BATCH*CHANS)        // 4096
#define FAN_IN    (NPATCH*NQ)          // 252
#define FPAD      256                  // head k padded to 256
#define NPAIR     136                  // 16*17/2

typedef unsigned long long ull;

// ---- packed f32x2 helpers (sm_103a) ---------------------------------------
__device__ __forceinline__ ull fma2(ull a, ull b, ull c) {
    ull d; asm("fma.rn.f32x2 %0, %1, %2, %3;" : "=l"(d) : "l"(a), "l"(b), "l"(c)); return d;
}
__device__ __forceinline__ ull mul2(ull a, ull b) {
    ull d; asm("mul.rn.f32x2 %0, %1, %2;" : "=l"(d) : "l"(a), "l"(b)); return d;
}
__device__ __forceinline__ ull add2(ull a, ull b) {
    ull d; asm("add.rn.f32x2 %0, %1, %2;" : "=l"(d) : "l"(a), "l"(b)); return d;
}
__device__ __forceinline__ ull pack2(float lo, float hi) {
    ull d; asm("mov.b64 %0, {%1, %2};" : "=l"(d) : "f"(lo), "f"(hi)); return d;
}
__device__ __forceinline__ float lo2(ull a) { return __uint_as_float((unsigned)(a & 0xffffffffull)); }
__device__ __forceinline__ float hi2(ull a) { return __uint_as_float((unsigned)(a >> 32)); }

// Scratch (device globals; no allocation allowed). 256 rows x 4096 = 4MB.
__device__ float  d_encT[FPAD * NCH];   // enc transposed [f][n]; rows 252..255 zero

// ---------------------------------------------------------------------------
// Kernel 1: encoder (logic unchanged; adds zeroing of pad rows 252..255).
// ---------------------------------------------------------------------------
__global__ __launch_bounds__(256) void enc_kernel(const float* __restrict__ x,
                                                  const float* __restrict__ weights) {
    __shared__ float2 sG[12][4];
    __shared__ float2 sU[16][16];
    __shared__ ulonglong2 sM[NPAIR * 2];

    int tid = threadIdx.x;
    int gtid = blockIdx.x * 256 + tid;

    // zero the 4 pad rows (rows 252..255 = 16384 floats = 8192 ull)
    if (gtid < 8192)
        ((ull*)(d_encT + (size_t)FAN_IN * NCH))[gtid] = 0ULL;

    if (tid < 12) {
        float phi   = weights[tid*3 + 0];
        float theta = weights[tid*3 + 1];
        float omega = weights[tid*3 + 2];
        float ct = cosf(0.5f*theta), st = sinf(0.5f*theta);
        float ap = 0.5f*(phi + omega);
        float am = 0.5f*(phi - omega);
        float cap = cosf(ap), sap = sinf(ap);
        float cam = cosf(am), sam = sinf(am);
        sG[tid][0] = make_float2( cap*ct, -sap*ct);
        sG[tid][1] = make_float2(-cam*st, -sam*st);
        sG[tid][2] = make_float2( cam*st, -sam*st);
        sG[tid][3] = make_float2( cap*ct,  sap*ct);
    }
    __syncthreads();

    if (tid < 16) {
        const int c = tid;
        float2 col[16];
        #pragma unroll
        for (int k = 0; k < 16; k++) col[k] = make_float2(k == c ? 1.f : 0.f, 0.f);

        #pragma unroll
        for (int l = 0; l < NLAYERS; l++) {
            #pragma unroll
            for (int w = 0; w < NQ; w++) {
                float2 m00 = sG[l*NQ + w][0], m01 = sG[l*NQ + w][1];
                float2 m10 = sG[l*NQ + w][2], m11 = sG[l*NQ + w][3];
                int bit = 1 << (3 - w);
                #pragma unroll
                for (int k0 = 0; k0 < 16; k0++) {
                    if (k0 & bit) continue;
                    int k1 = k0 | bit;
                    float2 a = col[k0], b = col[k1];
                    col[k0] = make_float2(m00.x*a.x - m00.y*a.y + m01.x*b.x - m01.y*b.y,
                                          m00.x*a.y + m00.y*a.x + m01.x*b.y + m01.y*b.x);
                    col[k1] = make_float2(m10.x*a.x - m10.y*a.y + m11.x*b.x - m11.y*b.y,
                                          m10.x*a.y + m10.y*a.x + m11.x*b.y + m11.y*b.x);
                }
            }
            int r = (l % (NQ - 1)) + 1;
            #pragma unroll
            for (int w = 0; w < NQ; w++) {
                int cb = 1 << (3 - w);
                int tb = 1 << (3 - ((w + r) & 3));
                #pragma unroll
                for (int k = 0; k < 16; k++) {
                    if ((k & cb) && !(k & tb)) {
                        float2 t = col[k]; col[k] = col[k | tb]; col[k | tb] = t;
                    }
                }
            }
        }
        #pragma unroll
        for (int k = 0; k < 16; k++) sU[k][c] = col[k];
    }
    __syncthreads();

    if (tid < NPAIR) {
        int a = 0, rem = tid;
        while (rem >= 16 - a) { rem -= 16 - a; a++; }
        int b = a + rem;

        float s[4] = {0.f, 0.f, 0.f, 0.f};
        #pragma unroll
        for (int k = 0; k < 16; k++) {
            float2 ua = sU[k][a], ub = sU[k][b];
            float re = ua.x*ub.x + ua.y*ub.y;
            #pragma unroll
            for (int i = 0; i < 4; i++)
                s[i] += ((k >> (3 - i)) & 1) ? -re : re;
        }
        float scale = (a == b) ? 1.f : 2.f;
        ulonglong2 q0, q1;
        q0.x = pack2(s[0]*scale, s[0]*scale); q0.y = pack2(s[1]*scale, s[1]*scale);
        q1.x = pack2(s[2]*scale, s[2]*scale); q1.y = pack2(s[3]*scale, s[3]*scale);
        sM[tid*2 + 0] = q0;
        sM[tid*2 + 1] = q1;
    }
    __syncthreads();

    int h = gtid & 2047;
    int j = gtid >> 11;
    int n0 = h << 1;
    int b  = n0 >> 7;
    int m  = n0 & 127;

    const ull* xp = (const ull*)(x + (size_t)b * (SEQ_LEN*CHANS)
                                   + (size_t)(j*STRIDE) * CHANS + m);
    const ull EPS2 = 0x358637bd358637bdULL;   // (1e-6f, 1e-6f)

    ull v[16];
    #pragma unroll
    for (int k = 0; k < 16; k++)
        v[k] = add2(xp[k * (CHANS/2)], EPS2);

    ull z0 = 0ULL, z1 = 0ULL, z2 = 0ULL, z3 = 0ULL, nrm2 = 0ULL;
    int p = 0;
    #pragma unroll
    for (int a = 0; a < 16; a++) {
        #pragma unroll
        for (int bb = a; bb < 16; bb++) {
            ull u = mul2(v[a], v[bb]);
            if (bb == a) nrm2 = add2(nrm2, u);
            ulonglong2 q0 = sM[2*p + 0];
            ulonglong2 q1 = sM[2*p + 1];
            z0 = fma2(u, q0.x, z0);
            z1 = fma2(u, q0.y, z1);
            z2 = fma2(u, q1.x, z2);
            z3 = fma2(u, q1.y, z3);
            p++;
        }
    }
    float inv0 = 1.0f / lo2(nrm2);
    float inv1 = 1.0f / hi2(nrm2);
    ull inv2 = pack2(inv0, inv1);

    ull* e = (ull*)(d_encT + (size_t)(j*4) * NCH + n0);
    e[0*(NCH/2)] = mul2(z0, inv2);
    e[1*(NCH/2)] = mul2(z1, inv2);
    e[2*(NCH/2)] = mul2(z2, inv2);
    e[3*(NCH/2)] = mul2(z3, inv2);
}

// ---------------------------------------------------------------------------
// GEMM segment helper: 2 data streams (p0,p1), 4 k's per chunk, 8 outputs.
// Per k: 2 LDG.64 + 4 broadcast LDS.128 + 16 FFMA2  =>  32 MACs.
// ---------------------------------------------------------------------------
__device__ __forceinline__ void gemm_seg(const ull* __restrict__ p0,
                                         const ull* __restrict__ p1,
                                         size_t stride,
                                         const ulonglong2* __restrict__ sW2,
                                         int krow0, int nchunks,
                                         ull acc[2][8]) {
    #pragma unroll 1
    for (int c = 0; c < nchunks; c++) {
        ull v0[4], v1[4];
        #pragma unroll
        for (int i = 0; i < 4; i++) {
            v0[i] = __ldg(p0 + (size_t)(c*4 + i) * stride);
            v1[i] = __ldg(p1 + (size_t)(c*4 + i) * stride);
        }
        #pragma unroll
        for (int i = 0; i < 4; i++) {
            int k = krow0 + c*4 + i;
            #pragma unroll
            for (int j = 0; j < 4; j++) {
                ulonglong2 q = sW2[k*4 + j];
                acc[0][2*j]   = fma2(v0[i], q.x, acc[0][2*j]);
                acc[0][2*j+1] = fma2(v0[i], q.y, acc[0][2*j+1]);
                acc[1][2*j]   = fma2(v1[i], q.x, acc[1][2*j]);
                acc[1][2*j+1] = fma2(v1[i], q.y, acc[1][2*j+1]);
            }
        }
    }
}

// ---------------------------------------------------------------------------
// Kernel 2: fused head+skip GEMM. 256 threads: cpg = tid&31 (2 channel-pairs:
// chans 2cpg,2cpg+1 and 64+2cpg,64+2cpg+1), g = tid>>5 = k-eighth over the
// unified padded k-space [0,768) = head[0,256) ++ skip[0,512). 16 f32x2 accs
// per thread; 8-way k-reduction through padded shared. grid (12,32)=384
// blocks -> all chip-resident in one wave at 3 blocks/SM cap.
// ---------------------------------------------------------------------------
#define OPB 8
__global__ __launch_bounds__(256, 3) void out_kernel(
    const float* __restrict__ x,
    const float* __restrict__ head_w, const float* __restrict__ head_b,
    const float* __restrict__ skip_w, const float* __restrict__ skip_b,
    float* __restrict__ out)
{
    __shared__ ull sW[(FPAD + SEQ_LEN) * OPB];   // 768*8*8B = 48KB exactly

    int tid = threadIdx.x;                 // 0..255
    int cpg = tid & 31;
    int g   = tid >> 5;                    // 0..7
    int b   = blockIdx.y;
    int o0  = blockIdx.x * OPB;

    // ---- stage dup-packed weights, k-major [k][r] (head pad rows = 0) ----
    for (int idx = tid; idx < FPAD * OPB; idx += 256) {
        int f = idx & 255, r = idx >> 8;
        float w = (f < FAN_IN) ? head_w[(size_t)(o0 + r) * FAN_IN + f] : 0.f;
        sW[f * OPB + r] = pack2(w, w);
    }
    for (int idx = tid; idx < SEQ_LEN * OPB; idx += 256) {
        int l = idx & 511, r = idx >> 9;
        float w = skip_w[(size_t)(o0 + r) * SEQ_LEN + l];
        sW[(FPAD + l) * OPB + r] = pack2(w, w);
    }
    __syncthreads();

    const ulonglong2* sW2 = (const ulonglong2*)sW;

    ull acc[2][8];
    #pragma unroll
    for (int s = 0; s < 2; s++)
        #pragma unroll
        for (int r = 0; r < 8; r++) acc[s][r] = 0ULL;

    const ull* ep = (const ull*)d_encT + (size_t)b * (CHANS/2) + cpg;
    const ull* xp = (const ull*)x + (size_t)b * (SEQ_LEN * CHANS / 2) + cpg;

    if (g < 2) {                                   // head k in [g*96, g*96+96)
        int f0 = g * 96;
        gemm_seg(ep + (size_t)f0 * (NCH/2), ep + (size_t)f0 * (NCH/2) + 32,
                 NCH/2, sW2, f0, 24, acc);
    } else if (g == 2) {                           // head [192,256) + skip [0,32)
        gemm_seg(ep + (size_t)192 * (NCH/2), ep + (size_t)192 * (NCH/2) + 32,
                 NCH/2, sW2, 192, 16, acc);
        gemm_seg(xp, xp + 32, CHANS/2, sW2, FPAD, 8, acc);
    } else {                                       // skip [32+(g-3)*96, +96)
        int l0 = 32 + (g - 3) * 96;
        gemm_seg(xp + (size_t)l0 * (CHANS/2), xp + (size_t)l0 * (CHANS/2) + 32,
                 CHANS/2, sW2, FPAD + l0, 24, acc);
    }

    // ---- 8-way k reduction through shared (reuse sW; padded stride 65) ----
    __syncthreads();
    ull* sR = sW;                          // needs 64*65*8B = 33.3KB
    #pragma unroll
    for (int s = 0; s < 2; s++) {
        int cp = cpg + 32 * s;
        #pragma unroll
        for (int r = 0; r < 8; r++)
            sR[cp * 65 + g * 8 + r] = acc[s][r];
    }
    __syncthreads();

    int cp = tid & 63;
    int q  = tid >> 6;                     // 0..3
    #pragma unroll
    for (int t = 0; t < 2; t++) {
        int oo = 2 * q + t;
        ull s = 0ULL;
        #pragma unroll
        for (int gg = 0; gg < 8; gg++)
            s = add2(s, sR[cp * 65 + gg * 8 + oo]);
        float bias = head_b[o0 + oo] + skip_b[o0 + oo];
        s = add2(s, pack2(bias, bias));
        ((ull*)out)[((size_t)b * PRED_LEN + o0 + oo) * (CHANS/2) + cp] = s;
    }
}

// ---------------------------------------------------------------------------
extern "C" void kernel_launch(void* const* d_in, const int* in_sizes, int n_in,
                              void* d_out, int out_size) {
    const float* x       = (const float*)d_in[0];
    const float* weights = (const float*)d_in[1];
    const float* head_w  = (const float*)d_in[2];
    const float* head_b  = (const float*)d_in[3];
    const float* skip_w  = (const float*)d_in[4];
    const float* skip_b  = (const float*)d_in[5];
    float* out = (float*)d_out;

    enc_kernel<<<(NPATCH * NCH / 2) / 256, 256>>>(x, weights);
    out_kernel<<<dim3(PRED_LEN / OPB, BATCH), 256>>>(x, head_w, head_b, skip_w, skip_b, out);
}

// round 9
// speedup vs baseline: 1.5000x; 1.0899x over previous
#include <cuda_runtime.h>
#include <cuda_bf16.h>
#include <math.h>

// Problem constants
#define SEQ_LEN   512
#define PRED_LEN  96
#define PATCH_LEN 16
#define STRIDE    8
#define NQ        4
#define NLAYERS   3
#define NPATCH    63           // (512-16)/8+1
#define BATCH     32
#define CHANS     128
#define NCH       (BATCH*CHANS)        // 4096
#define FAN_IN    (NPATCH*NQ)          // 252
#define FPAD      256                  // head k padded to 256
#define NPAIR     136                  // 16*17/2
#define KSEG      192                  // unified k per partial block (768/4)
#define NPART     (BATCH*PRED_LEN*CHANS/2)   // 196608 ull per k-quarter

typedef unsigned long long ull;

// ---- packed f32x2 helpers (sm_103a) ---------------------------------------
__device__ __forceinline__ ull fma2(ull a, ull b, ull c) {
    ull d; asm("fma.rn.f32x2 %0, %1, %2, %3;" : "=l"(d) : "l"(a), "l"(b), "l"(c)); return d;
}
__device__ __forceinline__ ull mul2(ull a, ull b) {
    ull d; asm("mul.rn.f32x2 %0, %1, %2;" : "=l"(d) : "l"(a), "l"(b)); return d;
}
__device__ __forceinline__ ull add2(ull a, ull b) {
    ull d; asm("add.rn.f32x2 %0, %1, %2;" : "=l"(d) : "l"(a), "l"(b)); return d;
}
__device__ __forceinline__ ull pack2(float lo, float hi) {
    ull d; asm("mov.b64 %0, {%1, %2};" : "=l"(d) : "f"(lo), "f"(hi)); return d;
}
__device__ __forceinline__ float lo2(ull a) { return __uint_as_float((unsigned)(a & 0xffffffffull)); }
__device__ __forceinline__ float hi2(ull a) { return __uint_as_float((unsigned)(a >> 32)); }

// Scratch (device globals; no allocation allowed)
__device__ float d_encT[FPAD * NCH];    // enc transposed [f][n]; rows 252..255 zero (4MB)
__device__ ull   d_part[4 * NPART];     // k-quarter partial outputs (6MB)

// ---------------------------------------------------------------------------
// Kernel 1: encoder, 4 channels per thread (LDG.128 data, sM LDS shared
// across two f32x2 streams). Per-block U-build prologue as before.
// ---------------------------------------------------------------------------
__global__ __launch_bounds__(256) void enc_kernel(const float* __restrict__ x,
                                                  const float* __restrict__ weights) {
    __shared__ float2 sG[12][4];
    __shared__ float2 sU[16][16];
    __shared__ ulonglong2 sM[NPAIR * 2];

    int tid = threadIdx.x;
    int gtid = blockIdx.x * 256 + tid;        // 252 blocks * 256 = 64512 threads

    // zero the 4 pad rows of encT (rows 252..255 = 8192 ull)
    if (gtid < 8192)
        ((ull*)(d_encT + (size_t)FAN_IN * NCH))[gtid] = 0ULL;

    if (tid < 12) {
        float phi   = weights[tid*3 + 0];
        float theta = weights[tid*3 + 1];
        float omega = weights[tid*3 + 2];
        float ct = cosf(0.5f*theta), st = sinf(0.5f*theta);
        float ap = 0.5f*(phi + omega);
        float am = 0.5f*(phi - omega);
        float cap = cosf(ap), sap = sinf(ap);
        float cam = cosf(am), sam = sinf(am);
        sG[tid][0] = make_float2( cap*ct, -sap*ct);
        sG[tid][1] = make_float2(-cam*st, -sam*st);
        sG[tid][2] = make_float2( cam*st, -sam*st);
        sG[tid][3] = make_float2( cap*ct,  sap*ct);
    }
    __syncthreads();

    if (tid < 16) {
        const int c = tid;
        float2 col[16];
        #pragma unroll
        for (int k = 0; k < 16; k++) col[k] = make_float2(k == c ? 1.f : 0.f, 0.f);

        #pragma unroll
        for (int l = 0; l < NLAYERS; l++) {
            #pragma unroll
            for (int w = 0; w < NQ; w++) {
                float2 m00 = sG[l*NQ + w][0], m01 = sG[l*NQ + w][1];
                float2 m10 = sG[l*NQ + w][2], m11 = sG[l*NQ + w][3];
                int bit = 1 << (3 - w);
                #pragma unroll
                for (int k0 = 0; k0 < 16; k0++) {
                    if (k0 & bit) continue;
                    int k1 = k0 | bit;
                    float2 a = col[k0], b = col[k1];
                    col[k0] = make_float2(m00.x*a.x - m00.y*a.y + m01.x*b.x - m01.y*b.y,
                                          m00.x*a.y + m00.y*a.x + m01.x*b.y + m01.y*b.x);
                    col[k1] = make_float2(m10.x*a.x - m10.y*a.y + m11.x*b.x - m11.y*b.y,
                                          m10.x*a.y + m10.y*a.x + m11.x*b.y + m11.y*b.x);
                }
            }
            int r = (l % (NQ - 1)) + 1;
            #pragma unroll
            for (int w = 0; w < NQ; w++) {
                int cb = 1 << (3 - w);
                int tb = 1 << (3 - ((w + r) & 3));
                #pragma unroll
                for (int k = 0; k < 16; k++) {
                    if ((k & cb) && !(k & tb)) {
                        float2 t = col[k]; col[k] = col[k | tb]; col[k | tb] = t;
                    }
                }
            }
        }
        #pragma unroll
        for (int k = 0; k < 16; k++) sU[k][c] = col[k];
    }
    __syncthreads();

    if (tid < NPAIR) {
        int a = 0, rem = tid;
        while (rem >= 16 - a) { rem -= 16 - a; a++; }
        int b = a + rem;

        float s[4] = {0.f, 0.f, 0.f, 0.f};
        #pragma unroll
        for (int k = 0; k < 16; k++) {
            float2 ua = sU[k][a], ub = sU[k][b];
            float re = ua.x*ub.x + ua.y*ub.y;
            #pragma unroll
            for (int i = 0; i < 4; i++)
                s[i] += ((k >> (3 - i)) & 1) ? -re : re;
        }
        float scale = (a == b) ? 1.f : 2.f;
        ulonglong2 q0, q1;
        q0.x = pack2(s[0]*scale, s[0]*scale); q0.y = pack2(s[1]*scale, s[1]*scale);
        q1.x = pack2(s[2]*scale, s[2]*scale); q1.y = pack2(s[3]*scale, s[3]*scale);
        sM[tid*2 + 0] = q0;
        sM[tid*2 + 1] = q1;
    }
    __syncthreads();

    // ---- main: 4 channels per thread (two f32x2 streams) ----
    int h = gtid & 1023;
    int j = gtid >> 10;
    int n0 = h << 2;                       // 4 channels: n0..n0+3
    int b  = n0 >> 7;
    int m  = n0 & 127;

    const ulonglong2* xp = (const ulonglong2*)(x + (size_t)b * (SEQ_LEN*CHANS)
                                                 + (size_t)(j*STRIDE) * CHANS + m);
    const ull EPS2 = 0x358637bd358637bdULL;   // (1e-6f, 1e-6f)

    ull v0[16], v1[16];
    #pragma unroll
    for (int k = 0; k < 16; k++) {
        ulonglong2 X = __ldg(xp + k * (CHANS/4));
        v0[k] = add2(X.x, EPS2);
        v1[k] = add2(X.y, EPS2);
    }

    ull z0[4] = {0,0,0,0}, z1[4] = {0,0,0,0};
    ull nrm0 = 0ULL, nrm1 = 0ULL;
    int p = 0;
    #pragma unroll
    for (int a = 0; a < 16; a++) {
        #pragma unroll
        for (int bb = a; bb < 16; bb++) {
            ull u0 = mul2(v0[a], v0[bb]);
            ull u1 = mul2(v1[a], v1[bb]);
            if (bb == a) { nrm0 = add2(nrm0, u0); nrm1 = add2(nrm1, u1); }
            ulonglong2 q0 = sM[2*p + 0];
            ulonglong2 q1 = sM[2*p + 1];
            z0[0] = fma2(u0, q0.x, z0[0]);  z1[0] = fma2(u1, q0.x, z1[0]);
            z0[1] = fma2(u0, q0.y, z0[1]);  z1[1] = fma2(u1, q0.y, z1[1]);
            z0[2] = fma2(u0, q1.x, z0[2]);  z1[2] = fma2(u1, q1.x, z1[2]);
            z0[3] = fma2(u0, q1.y, z0[3]);  z1[3] = fma2(u1, q1.y, z1[3]);
            p++;
        }
    }
    ull inv0 = pack2(1.0f / lo2(nrm0), 1.0f / hi2(nrm0));
    ull inv1 = pack2(1.0f / lo2(nrm1), 1.0f / hi2(nrm1));

    #pragma unroll
    for (int i = 0; i < 4; i++) {
        ulonglong2 o;
        o.x = mul2(z0[i], inv0);
        o.y = mul2(z1[i], inv1);
        *(ulonglong2*)(d_encT + (size_t)(j*4 + i) * NCH + n0) = o;
    }
}

// ---------------------------------------------------------------------------
// GEMM segment: compile-time stride (immediate-offset LDG, 1 IADD per chunk).
// Per k: 2 LDG.64 + 4 broadcast LDS.128 + 16 FFMA2 => 32 MACs.
// ---------------------------------------------------------------------------
template<int STRIDE_ULL>
__device__ __forceinline__ void gemm_seg(const ull* __restrict__ p, int nchunks,
                                         const ulonglong2* __restrict__ sw,
                                         ull acc[2][8]) {
    #pragma unroll 1
    for (int c = 0; c < nchunks; c++) {
        ull v0[4], v1[4];
        #pragma unroll
        for (int i = 0; i < 4; i++) {
            v0[i] = __ldg(p + i * STRIDE_ULL);
            v1[i] = __ldg(p + i * STRIDE_ULL + 32);
        }
        #pragma unroll
        for (int i = 0; i < 4; i++) {
            #pragma unroll
            for (int j = 0; j < 4; j++) {
                ulonglong2 q = sw[i*4 + j];
                acc[0][2*j]   = fma2(v0[i], q.x, acc[0][2*j]);
                acc[0][2*j+1] = fma2(v0[i], q.y, acc[0][2*j+1]);
                acc[1][2*j]   = fma2(v1[i], q.x, acc[1][2*j]);
                acc[1][2*j+1] = fma2(v1[i], q.y, acc[1][2*j+1]);
            }
        }
        p  += 4 * STRIDE_ULL;
        sw += 16;
    }
}

// ---------------------------------------------------------------------------
// Kernel 2: partial fused GEMM over one k-quarter of the unified k-space
// [0,768) = head-padded[0,256) ++ skip[0,512).
// grid (12 o-tiles, 32 b, 4 kq), 256 threads: cpg=tid&31 (2 channel-pair
// streams), g=tid>>5 (k-24-slice). 8-way in-block reduction -> d_part.
// ---------------------------------------------------------------------------
#define OPB 8
__global__ __launch_bounds__(256, 4) void out_partial(
    const float* __restrict__ x,
    const float* __restrict__ head_w, const float* __restrict__ skip_w)
{
    __shared__ ull sS[64 * 65];            // 33.3KB; first 1536 = staged weights

    int tid = threadIdx.x;
    int cpg = tid & 31;
    int g   = tid >> 5;                    // 0..7
    int b   = blockIdx.y;
    int o0  = blockIdx.x * OPB;
    int kq  = blockIdx.z;

    // ---- stage this quarter's weights dup-packed: sW[kk*8 + r] ----
    #pragma unroll
    for (int it = 0; it < 6; it++) {
        int idx = it * 256 + tid;          // < 1536
        int r  = idx / KSEG;
        int kk = idx - r * KSEG;
        int k  = kq * KSEG + kk;           // unified k
        float w;
        if (k < FPAD) w = (k < FAN_IN) ? head_w[(o0 + r) * FAN_IN + k] : 0.f;
        else          w = skip_w[(o0 + r) * SEQ_LEN + (k - FPAD)];
        sS[kk * 8 + r] = pack2(w, w);
    }
    __syncthreads();

    ull acc[2][8];
    #pragma unroll
    for (int s = 0; s < 2; s++)
        #pragma unroll
        for (int r = 0; r < 8; r++) acc[s][r] = 0ULL;

    int k0u = kq * KSEG + g * 24;          // unified k start for this thread
    const ulonglong2* sw = (const ulonglong2*)sS + (g * 24) * 4;

    int hk = FPAD - k0u;                   // head elements within [k0u, k0u+24)
    hk = hk < 0 ? 0 : (hk > 24 ? 24 : hk);
    int ch = hk >> 2;                      // head chunks (of 4)

    if (ch > 0) {
        const ull* ep = (const ull*)d_encT + (size_t)k0u * (NCH/2) + b * (CHANS/2) + cpg;
        gemm_seg<NCH/2>(ep, ch, sw, acc);
    }
    if (ch < 6) {
        int l0 = k0u + hk - FPAD;          // first skip row
        const ull* xp = (const ull*)x + ((size_t)b * SEQ_LEN + l0) * (CHANS/2) + cpg;
        gemm_seg<CHANS/2>(xp, 6 - ch, sw + hk * 4, acc);
    }

    // ---- 8-way k reduction (padded stride 65) ----
    __syncthreads();
    #pragma unroll
    for (int s = 0; s < 2; s++) {
        int cp = cpg + 32 * s;
        #pragma unroll
        for (int r = 0; r < 8; r++)
            sS[cp * 65 + g * 8 + r] = acc[s][r];
    }
    __syncthreads();

    int cp = tid & 63;
    int q  = tid >> 6;
    #pragma unroll
    for (int t = 0; t < 2; t++) {
        int oo = 2 * q + t;
        ull s = 0ULL;
        #pragma unroll
        for (int gg = 0; gg < 8; gg++)
            s = add2(s, sS[cp * 65 + gg * 8 + oo]);
        d_part[(size_t)kq * NPART + (((size_t)b * PRED_LEN + o0 + oo) * (CHANS/2) + cp)] = s;
    }
}

// ---------------------------------------------------------------------------
// Kernel 3: reduce 4 k-quarter partials + bias -> out. L2-hot, ~3us.
// ---------------------------------------------------------------------------
__global__ __launch_bounds__(256) void out_reduce(
    const float* __restrict__ head_b, const float* __restrict__ skip_b,
    float* __restrict__ out)
{
    int idx = blockIdx.x * 256 + threadIdx.x;     // [0, NPART)
    int o = (idx >> 6) % PRED_LEN;
    ull s = add2(add2(__ldg(d_part + idx),             __ldg(d_part + idx + NPART)),
                 add2(__ldg(d_part + idx + 2*NPART),   __ldg(d_part + idx + 3*NPART)));
    float bias = head_b[o] + skip_b[o];
    ((ull*)out)[idx] = add2(s, pack2(bias, bias));
}

// ---------------------------------------------------------------------------
extern "C" void kernel_launch(void* const* d_in, const int* in_sizes, int n_in,
                              void* d_out, int out_size) {
    const float* x       = (const float*)d_in[0];
    const float* weights = (const float*)d_in[1];
    const float* head_w  = (const float*)d_in[2];
    const float* head_b  = (const float*)d_in[3];
    const float* skip_w  = (const float*)d_in[4];
    const float* skip_b  = (const float*)d_in[5];
    float* out = (float*)d_out;

    enc_kernel<<<(NPATCH * NCH / 4) / 256, 256>>>(x, weights);
    out_partial<<<dim3(PRED_LEN / OPB, BATCH, 4), 256>>>(x, head_w, skip_w);
    out_reduce<<<NPART / 256, 256>>>(head_b, skip_b, out);
}